// round 8
// baseline (speedup 1.0000x reference)
#include <cuda_runtime.h>
#include <cstdint>
#include <cstddef>

// ---------------------------------------------------------------------------
// 20 independent GEMMs (block-diagonal ensemble linear)
//   x:[32768,4000] f32, W:[2000,4000] f32, out:[32768,2000] f32
//   block n: out[:,n*100:+100] = x[:,n*200:+200] @ W[n*100:+100, n*200:+200]^T
//
// R8: persistent-ish CTAs (grid 20x7). W-block resident in SMEM (converted
// tf32-RNA once). 6-slot cp.async ring for A keeps ~112KB of DRAM loads in
// flight per SM. A fed to HMMA as raw f32 bits (HW tf32 truncation) -> no
// per-fragment CVTs in the mainloop.
// ---------------------------------------------------------------------------

static constexpr int BATCH   = 32768;
static constexpr int NUM     = 20;
static constexpr int IN_SZ   = 200;               // K per block
static constexpr int OUT_SZ  = 100;               // N per block (real)
static constexpr int X_LD    = NUM * IN_SZ;       // 4000
static constexpr int W_LD    = NUM * IN_SZ;       // 4000
static constexpr int OUT_LD  = NUM * OUT_SZ;      // 2000

static constexpr int M_TILE  = 128;
static constexpr int N_TILE  = 112;               // padded 100 -> 112
static constexpr int KC      = 40;                // K chunk
static constexpr int KCH_PER_MT = IN_SZ / KC;     // 5
static constexpr int MT_PER_N   = BATCH / M_TILE; // 256
static constexpr int CTAS_PER_N = 7;              // grid 20*7 = 140 CTAs

static constexpr int NSLOT   = 6;                 // A ring depth
static constexpr int STR_A   = 44;                // A slot row stride (floats)
static constexpr int STR_B   = 204;               // B row stride (floats); 204%32=12 -> conflict-free

static constexpr int A_ELEMS = M_TILE * STR_A;    // 5632 floats / slot
static constexpr int B_ELEMS = N_TILE * STR_B;    // 22848 floats
static constexpr int SMEM_FLOATS = B_ELEMS + NSLOT * A_ELEMS;   // 56640
static constexpr int SMEM_BYTES  = SMEM_FLOATS * 4;             // 226560

static constexpr int THREADS = 256;               // 8 warps: 4(M) x 2(N)
// warp tile 32(M) x 56(N): 2 m16 x 7 n8 per k8 step

// ---------------------------------------------------------------------------
__device__ __forceinline__ uint32_t smem_u32(const void* p) {
    uint32_t a;
    asm("{ .reg .u64 t; cvta.to.shared.u64 t, %1; cvt.u32.u64 %0, t; }"
        : "=r"(a) : "l"(p));
    return a;
}
__device__ __forceinline__ void cp16(uint32_t dst, const float* src) {
    asm volatile("cp.async.cg.shared.global [%0], [%1], 16;"
                 :: "r"(dst), "l"(src));
}
#define CP_COMMIT() asm volatile("cp.async.commit_group;" ::: "memory")
#define CP_WAIT(n)  asm volatile("cp.async.wait_group %0;" :: "n"(n) : "memory")

__device__ __forceinline__ float f2tf32_rna(float f) {
    uint32_t r;
    asm("cvt.rna.tf32.f32 %0, %1;" : "=r"(r) : "f"(f));
    return __uint_as_float(r);
}

// D(16x8,f32) += A(16x8,tf32) * B(8x8,tf32); raw f32 bit patterns in a/b regs
__device__ __forceinline__ void mma_tf32(float c[4],
                                         uint32_t a0, uint32_t a1, uint32_t a2, uint32_t a3,
                                         uint32_t b0, uint32_t b1) {
    asm volatile(
        "mma.sync.aligned.m16n8k8.row.col.f32.tf32.tf32.f32 "
        "{%0,%1,%2,%3}, {%4,%5,%6,%7}, {%8,%9}, {%0,%1,%2,%3};"
        : "+f"(c[0]), "+f"(c[1]), "+f"(c[2]), "+f"(c[3])
        : "r"(a0), "r"(a1), "r"(a2), "r"(a3), "r"(b0), "r"(b1));
}

// ---------------------------------------------------------------------------
// One CTA = ensemble block n, M-tiles {cta_m, cta_m+7, ...}
// ---------------------------------------------------------------------------
__global__ void __launch_bounds__(THREADS, 1)
ensemble_linear_mma_kernel(const float* __restrict__ x,
                           const float* __restrict__ W,
                           float* __restrict__ out) {
    extern __shared__ float smem[];
    float* Bsm = smem;                     // [112][204], resident all kernel
    float* Asm = smem + B_ELEMS;           // [6][128*44] ring
    const uint32_t a_base = smem_u32(Asm);

    const int tid = threadIdx.x;
    const int wid = tid >> 5;
    const int lid = tid & 31;
    const int g   = lid >> 2;    // 0..7
    const int tg  = lid & 3;     // 0..3
    const int wm  = wid >> 1;    // 0..3 (M)
    const int wn  = wid & 1;     // 0..1 (N)

    const int n     = blockIdx.x;          // 0..19
    const int cta_m = blockIdx.y;          // 0..6
    const int n_mt  = (MT_PER_N - cta_m + CTAS_PER_N - 1) / CTAS_PER_N;  // 36/37
    const int total_chunks = n_mt * KCH_PER_MT;

    // ---- one-time B load: W block -> SMEM, RNA-rounded to tf32 grid --------
    {
        const float* wbase = W + (size_t)n * OUT_SZ * W_LD + (size_t)n * IN_SZ;
        // 100 rows x 50 float4
        for (int idx = tid; idx < OUT_SZ * 50; idx += THREADS) {
            int r  = idx / 50;
            int c4 = idx - r * 50;
            float4 v = *(const float4*)(wbase + (size_t)r * W_LD + c4 * 4);
            v.x = f2tf32_rna(v.x); v.y = f2tf32_rna(v.y);
            v.z = f2tf32_rna(v.z); v.w = f2tf32_rna(v.w);
            *(float4*)(Bsm + r * STR_B + c4 * 4) = v;   // 204*4B = 16B-aligned rows
        }
        // zero padding rows 100..111
        for (int i = tid; i < 12 * STR_B; i += THREADS) {
            int r = 100 + i / STR_B;
            int c = i - (i / STR_B) * STR_B;
            Bsm[r * STR_B + c] = 0.0f;
        }
    }

    const float* xbase = x + (size_t)n * IN_SZ;

    // ---- A chunk producer (cp.async) ---------------------------------------
    auto produce = [&](int c) {
        if (c < total_chunks) {
            int ml = c / KCH_PER_MT;
            int kc = c - ml * KCH_PER_MT;
            int mt = cta_m + ml * CTAS_PER_N;
            const float* xs = xbase + (size_t)mt * M_TILE * X_LD + kc * KC;
            uint32_t dst = a_base + (uint32_t)((c % NSLOT) * A_ELEMS) * 4u;
            // 128 rows x 10 float4 = 1280 ops -> 5 per thread
            #pragma unroll
            for (int j = 0; j < 5; ++j) {
                int idx = tid + j * THREADS;
                int r = idx / 10;
                int i = idx - r * 10;
                cp16(dst + (uint32_t)(r * STR_A + i * 4) * 4u,
                     xs + (size_t)r * X_LD + i * 4);
            }
        }
        CP_COMMIT();   // commit even when empty: keeps wait_group counting sound
    };

    float acc[2][7][4];
    #pragma unroll
    for (int t = 0; t < 2; ++t)
        #pragma unroll
        for (int j = 0; j < 7; ++j)
            #pragma unroll
            for (int q = 0; q < 4; ++q) acc[t][j][q] = 0.0f;

    // B also guarded by first __syncthreads inside the loop.
    // Prologue: fill 5 of 6 ring slots.
    #pragma unroll
    for (int p = 0; p < NSLOT - 1; ++p) produce(p);

    // ---- mainloop: one chunk per iteration ---------------------------------
    for (int c = 0; c < total_chunks; ++c) {
        CP_WAIT(4);            // chunk c resident (<=4 newer groups pending)
        __syncthreads();       // all warps: chunk c visible AND chunk c-1 consumed

        produce(c + NSLOT - 1);  // writes slot (c-1)%6 — safe after the sync

        const int slot = c % NSLOT;
        const float* Ab = Asm + slot * A_ELEMS;
        const int kc = c % KCH_PER_MT;
        const int kg = kc * KC;

        #pragma unroll
        for (int ks = 0; ks < KC / 8; ++ks) {
            const int k0 = ks * 8;
            uint32_t a[2][4];
            #pragma unroll
            for (int t = 0; t < 2; ++t) {
                const uint32_t* ap = (const uint32_t*)(Ab + (wm * 32 + t * 16 + g) * STR_A + k0 + tg);
                a[t][0] = ap[0];
                a[t][1] = ap[8 * STR_A];
                a[t][2] = ap[4];
                a[t][3] = ap[8 * STR_A + 4];
            }
            uint32_t b[7][2];
            #pragma unroll
            for (int j = 0; j < 7; ++j) {
                const uint32_t* bp = (const uint32_t*)(Bsm + (wn * 56 + j * 8 + g) * STR_B + kg + k0 + tg);
                b[j][0] = bp[0];
                b[j][1] = bp[4];
            }
            #pragma unroll
            for (int t = 0; t < 2; ++t)
                #pragma unroll
                for (int j = 0; j < 7; ++j)
                    mma_tf32(acc[t][j], a[t][0], a[t][1], a[t][2], a[t][3],
                             b[j][0], b[j][1]);
        }

        // ---- per-M-tile epilogue after last k-chunk ------------------------
        if (kc == KCH_PER_MT - 1) {
            const int mt = cta_m + (c / KCH_PER_MT) * CTAS_PER_N;
            const int row_base = mt * M_TILE + wm * 32;
            #pragma unroll
            for (int t = 0; t < 2; ++t) {
                const int r0 = row_base + t * 16 + g;
                float* orow = out + (size_t)r0 * OUT_LD + (size_t)n * OUT_SZ;
                #pragma unroll
                for (int j = 0; j < 7; ++j) {
                    const int cgl = wn * 56 + j * 8 + 2 * tg;   // even, 0..110
                    if (cgl < OUT_SZ) {
                        *(float2*)(orow + cgl) =
                            make_float2(acc[t][j][0], acc[t][j][1]);
                        *(float2*)(orow + (size_t)8 * OUT_LD + cgl) =
                            make_float2(acc[t][j][2], acc[t][j][3]);
                    }
                    #pragma unroll
                    for (int q = 0; q < 4; ++q) acc[t][j][q] = 0.0f;
                }
            }
        }
    }
}

// ---------------------------------------------------------------------------
extern "C" void kernel_launch(void* const* d_in, const int* in_sizes, int n_in,
                              void* d_out, int out_size) {
    const float* x = (const float*)d_in[0];   // [32768, 4000]
    const float* W = (const float*)d_in[1];   // [2000, 4000]
    float* out = (float*)d_out;               // [32768, 2000]

    cudaFuncSetAttribute(ensemble_linear_mma_kernel,
                         cudaFuncAttributeMaxDynamicSharedMemorySize,
                         SMEM_BYTES);

    dim3 grid(NUM, CTAS_PER_N, 1);            // 20 x 7 = 140 CTAs
    ensemble_linear_mma_kernel<<<grid, THREADS, SMEM_BYTES>>>(x, W, out);
}